// round 12
// baseline (speedup 1.0000x reference)
#include <cuda_runtime.h>
#include <cstdint>
#include <cfloat>

#define NN 40000
#define EE 640000
#define GG 64
#define DD 128
#define HH 128
#define OO 10
#define NPW 4            // nodes per warp in k_agg
#define SBLK 157         // scan blocks: ceil(40000/256)

typedef unsigned long long ull;

// ---------------- scratch (static device globals; no allocations) ----------------
// INVARIANTS across graph replays (module-load zeroed, restored by last reader):
//   g_degi == 0   (re-zeroed by k_scanC)
//   g_addpool == 0, g_maxpool == 0, g_counts == 0  (re-zeroed by k_final)
__device__ float    g_h[NN * HH];      // x @ W_gcn (L2-resident, 20.5 MB)
__device__ int      g_degi[NN];
__device__ float    g_dinv[NN];
__device__ int      g_off[NN + 1];     // CSR row offsets (by dst)
__device__ int      g_cursor[NN];
__device__ int2     g_edge[EE];        // CSR: (src, bits(dinv[src]))
__device__ int      g_bsum[SBLK];      // scan partials
__device__ float    g_addpool[GG * HH];
__device__ unsigned g_maxpool[GG * HH];
__device__ int      g_counts[GG];

// order-preserving float <-> unsigned encoding for atomicMax
__device__ __forceinline__ unsigned fkey(float f) {
    int i = __float_as_int(f);
    return (unsigned)(i ^ ((i >> 31) | 0x80000000));
}
__device__ __forceinline__ float fdec(unsigned k) {
    int i = (k & 0x80000000u) ? (int)(k ^ 0x80000000u) : (int)(~k);
    return __int_as_float(i);
}

// packed f32x2 helpers (PTX-only; ptxas never emits FFMA2 from C++)
__device__ __forceinline__ ull pk2(float lo, float hi) {
    ull r; asm("mov.b64 %0, {%1, %2};" : "=l"(r) : "f"(lo), "f"(hi)); return r;
}
__device__ __forceinline__ void upk2(ull v, float& lo, float& hi) {
    asm("mov.b64 {%0, %1}, %2;" : "=f"(lo), "=f"(hi) : "l"(v));
}
__device__ __forceinline__ ull ffma2(ull a, ull b, ull c) {
    ull d; asm("fma.rn.f32x2 %0, %1, %2, %3;" : "=l"(d) : "l"(a), "l"(b), "l"(c));
    return d;
}

// ---------------- kernels ----------------
// 4 edges per thread via int4 loads (EE % 4 == 0): 4 atomics in flight.
__global__ void k_deg(const int* __restrict__ ei) {
    int t = blockIdx.x * blockDim.x + threadIdx.x;
    if (t >= EE / 4) return;
    int4 d = ((const int4*)(ei + EE))[t];
    atomicAdd(&g_degi[d.x], 1);
    atomicAdd(&g_degi[d.y], 1);
    atomicAdd(&g_degi[d.z], 1);
    atomicAdd(&g_degi[d.w], 1);
}

// Phase A: block-local exclusive prefix + per-block sums.
__global__ void k_scanA() {
    __shared__ int s[256];
    int t = threadIdx.x;
    int idx = blockIdx.x * 256 + t;
    int d = (idx < NN) ? g_degi[idx] : 0;
    s[t] = d;
    __syncthreads();
#pragma unroll
    for (int o = 1; o < 256; o <<= 1) {
        int v = (t >= o) ? s[t - o] : 0;
        __syncthreads();
        s[t] += v;
        __syncthreads();
    }
    if (idx < NN) g_off[idx] = s[t] - d;      // block-local exclusive prefix
    if (t == 255) g_bsum[blockIdx.x] = s[255];
}

// Phase B+C merged: each block redundantly computes its exclusive base from
// g_bsum (<=5 loads/lane + warp reduce), then finalizes offsets/cursors/dinv
// and re-zeros g_degi (zero-on-entry invariant for next replay).
__global__ void k_scanC() {
    __shared__ int sbase;
    int t = threadIdx.x;
    if (t < 32) {
        int sum = 0;
        for (int i = t; i < blockIdx.x; i += 32) sum += g_bsum[i];
#pragma unroll
        for (int o = 16; o; o >>= 1) sum += __shfl_xor_sync(0xffffffffu, sum, o);
        if (t == 0) sbase = sum;
    }
    __syncthreads();
    int idx = blockIdx.x * 256 + t;
    if (idx < NN) {
        int o = g_off[idx] + sbase;
        int d = g_degi[idx];
        g_off[idx] = o;
        g_cursor[idx] = o;
        g_dinv[idx] = rsqrtf((float)d + 1.0f);
        g_degi[idx] = 0;
    }
    if (blockIdx.x == 0 && t == 0) g_off[NN] = EE;   // total is a constant
}

// 4 edges per thread: 4 independent cursor atomics + 4 stores in flight.
__global__ void k_place(const int* __restrict__ ei) {
    int t = blockIdx.x * blockDim.x + threadIdx.x;
    if (t >= EE / 4) return;
    int4 s4 = ((const int4*)ei)[t];             // 4 src
    int4 d4 = ((const int4*)(ei + EE))[t];      // 4 dst
    int p0 = atomicAdd(&g_cursor[d4.x], 1);
    int p1 = atomicAdd(&g_cursor[d4.y], 1);
    int p2 = atomicAdd(&g_cursor[d4.z], 1);
    int p3 = atomicAdd(&g_cursor[d4.w], 1);
    float c0 = g_dinv[s4.x], c1 = g_dinv[s4.y];
    float c2 = g_dinv[s4.z], c3 = g_dinv[s4.w];
    g_edge[p0] = make_int2(s4.x, __float_as_int(c0));
    g_edge[p1] = make_int2(s4.y, __float_as_int(c1));
    g_edge[p2] = make_int2(s4.z, __float_as_int(c2));
    g_edge[p3] = make_int2(s4.w, __float_as_int(c3));
}

// h = x @ W. 64x128 tile, 256 threads, packed f32x2 FFMA (row-pair accumulators).
__global__ void k_gemm(const float* __restrict__ x, const float* __restrict__ W) {
    extern __shared__ float sm[];
    float* Ws = sm;                 // 128*128
    float* Xs = sm + DD * HH;       // 16 * 72 (transposed x tile)
    const int XLD = 72;
    int tid = threadIdx.x;
    int row0 = blockIdx.x * 64;

    for (int i = tid; i < (DD * HH) / 4; i += 256)
        ((float4*)Ws)[i] = ((const float4*)W)[i];

    int tx = tid & 31;              // cols tx*4 .. tx*4+3
    int ty = tid >> 5;              // rows ty*8 .. ty*8+7 (as 4 pairs)
    ull acc[4][4];                  // [row-pair][col]
#pragma unroll
    for (int rp = 0; rp < 4; rp++)
#pragma unroll
        for (int c = 0; c < 4; c++) acc[rp][c] = 0ULL;

    int lr = tid >> 2, lk = tid & 3;
    for (int kt = 0; kt < DD; kt += 16) {
        __syncthreads();
        float4 xv = *(const float4*)(x + (size_t)(row0 + lr) * DD + kt + lk * 4);
        Xs[(lk * 4 + 0) * XLD + lr] = xv.x;
        Xs[(lk * 4 + 1) * XLD + lr] = xv.y;
        Xs[(lk * 4 + 2) * XLD + lr] = xv.z;
        Xs[(lk * 4 + 3) * XLD + lr] = xv.w;
        __syncthreads();
#pragma unroll
        for (int kk = 0; kk < 16; kk++) {
            float4 wv = *(const float4*)(Ws + (kt + kk) * HH + tx * 4);
            ulonglong2 xa = *(const ulonglong2*)(Xs + kk * XLD + ty * 8);
            ulonglong2 xb = *(const ulonglong2*)(Xs + kk * XLD + ty * 8 + 4);
            ull xp[4] = {xa.x, xa.y, xb.x, xb.y};
            ull w0 = pk2(wv.x, wv.x), w1 = pk2(wv.y, wv.y);
            ull w2 = pk2(wv.z, wv.z), w3 = pk2(wv.w, wv.w);
#pragma unroll
            for (int rp = 0; rp < 4; rp++) {
                acc[rp][0] = ffma2(xp[rp], w0, acc[rp][0]);
                acc[rp][1] = ffma2(xp[rp], w1, acc[rp][1]);
                acc[rp][2] = ffma2(xp[rp], w2, acc[rp][2]);
                acc[rp][3] = ffma2(xp[rp], w3, acc[rp][3]);
            }
        }
    }
#pragma unroll
    for (int rp = 0; rp < 4; rp++) {
        float l0, h0, l1, h1, l2, h2, l3, h3;
        upk2(acc[rp][0], l0, h0);
        upk2(acc[rp][1], l1, h1);
        upk2(acc[rp][2], l2, h2);
        upk2(acc[rp][3], l3, h3);
        size_t r = (size_t)(row0 + ty * 8 + 2 * rp) * HH + tx * 4;
        *(float4*)(g_h + r)      = make_float4(l0, l1, l2, l3);
        *(float4*)(g_h + r + HH) = make_float4(h0, h1, h2, h3);
    }
}

__device__ __forceinline__ void pool_flush(int g, int f, float4 padd, float4 pmax,
                                           int pcnt, int lane) {
    float* p = g_addpool + g * HH + f;
    asm volatile("red.global.add.v4.f32 [%0], {%1, %2, %3, %4};"
                 :: "l"(p), "f"(padd.x), "f"(padd.y), "f"(padd.z), "f"(padd.w)
                 : "memory");
    unsigned* mp = g_maxpool + g * HH + f;
    atomicMax(mp + 0, fkey(pmax.x));
    atomicMax(mp + 1, fkey(pmax.y));
    atomicMax(mp + 2, fkey(pmax.z));
    atomicMax(mp + 3, fkey(pmax.w));
    if (lane == 0) atomicAdd(&g_counts[g], pcnt);
}

// One warp per NPW consecutive nodes: 2-wide CSR gather-reduce + self loop +
// bias + ReLU + LayerNorm + register pooling. (R6 measured-best shape.)
__global__ void __launch_bounds__(256) k_agg(const int* __restrict__ batch,
                                             const float* __restrict__ bgcn,
                                             const float* __restrict__ gamma,
                                             const float* __restrict__ beta) {
    int warp = blockIdx.x * 8 + (threadIdx.x >> 5);
    int n0 = warp * NPW;
    if (n0 >= NN) return;
    int lane = threadIdx.x & 31;
    int f = lane * 4;

    float4 bb = *(const float4*)(bgcn + f);
    float4 ga = *(const float4*)(gamma + f);
    float4 be = *(const float4*)(beta + f);

    float4 padd = make_float4(0.f, 0.f, 0.f, 0.f);
    float4 pmax = make_float4(-FLT_MAX, -FLT_MAX, -FLT_MAX, -FLT_MAX);
    int pcnt = 0;
    int curg = __ldg(&batch[n0]);

#pragma unroll
    for (int k = 0; k < NPW; k++) {
        int n = n0 + k;
        int g = __ldg(&batch[n]);
        if (g != curg) {
            pool_flush(curg, f, padd, pmax, pcnt, lane);
            padd = make_float4(0.f, 0.f, 0.f, 0.f);
            pmax = make_float4(-FLT_MAX, -FLT_MAX, -FLT_MAX, -FLT_MAX);
            pcnt = 0;
            curg = g;
        }
        int s = __ldg(&g_off[n]);
        int e = __ldg(&g_off[n + 1]);
        float4 a0 = make_float4(0.f, 0.f, 0.f, 0.f);
        float4 a1 = make_float4(0.f, 0.f, 0.f, 0.f);
        int j = s;
        if ((j & 1) && j < e) {             // align to int4 boundary
            int2 p = __ldg(&g_edge[j]);
            float c = __int_as_float(p.y);
            float4 v = *(const float4*)(g_h + (size_t)p.x * HH + f);
            a0.x = fmaf(c, v.x, a0.x); a0.y = fmaf(c, v.y, a0.y);
            a0.z = fmaf(c, v.z, a0.z); a0.w = fmaf(c, v.w, a0.w);
            j++;
        }
        for (; j + 2 <= e; j += 2) {        // 2 independent gathers in flight
            int4 q = *(const int4*)(g_edge + j);   // two edges, one broadcast ld
            float4 v0 = *(const float4*)(g_h + (size_t)q.x * HH + f);
            float4 v1 = *(const float4*)(g_h + (size_t)q.z * HH + f);
            float c0 = __int_as_float(q.y), c1 = __int_as_float(q.w);
            a0.x = fmaf(c0, v0.x, a0.x); a0.y = fmaf(c0, v0.y, a0.y);
            a0.z = fmaf(c0, v0.z, a0.z); a0.w = fmaf(c0, v0.w, a0.w);
            a1.x = fmaf(c1, v1.x, a1.x); a1.y = fmaf(c1, v1.y, a1.y);
            a1.z = fmaf(c1, v1.z, a1.z); a1.w = fmaf(c1, v1.w, a1.w);
        }
        if (j < e) {                        // tail (at most 1)
            int2 p = __ldg(&g_edge[j]);
            float c = __int_as_float(p.y);
            float4 v = *(const float4*)(g_h + (size_t)p.x * HH + f);
            a0.x = fmaf(c, v.x, a0.x); a0.y = fmaf(c, v.y, a0.y);
            a0.z = fmaf(c, v.z, a0.z); a0.w = fmaf(c, v.w, a0.w);
        }
        float4 acc = make_float4(a0.x + a1.x, a0.y + a1.y,
                                 a0.z + a1.z, a0.w + a1.w);

        float di = g_dinv[n];
        float4 hv = *(const float4*)(g_h + (size_t)n * HH + f);
        float4 v;
        v.x = fmaxf(fmaf(fmaf(hv.x, di, acc.x), di, bb.x), 0.f);
        v.y = fmaxf(fmaf(fmaf(hv.y, di, acc.y), di, bb.y), 0.f);
        v.z = fmaxf(fmaf(fmaf(hv.z, di, acc.z), di, bb.z), 0.f);
        v.w = fmaxf(fmaf(fmaf(hv.w, di, acc.w), di, bb.w), 0.f);

        float ssum = v.x + v.y + v.z + v.w;
        float qsum = v.x * v.x + v.y * v.y + v.z * v.z + v.w * v.w;
#pragma unroll
        for (int o = 16; o; o >>= 1) {
            ssum += __shfl_xor_sync(0xffffffffu, ssum, o);
            qsum += __shfl_xor_sync(0xffffffffu, qsum, o);
        }
        float mean = ssum * (1.f / 128.f);
        float var  = qsum * (1.f / 128.f) - mean * mean;
        float rstd = rsqrtf(var + 1e-5f);

        float4 y;
        y.x = fmaf((v.x - mean) * rstd, ga.x, be.x);
        y.y = fmaf((v.y - mean) * rstd, ga.y, be.y);
        y.z = fmaf((v.z - mean) * rstd, ga.z, be.z);
        y.w = fmaf((v.w - mean) * rstd, ga.w, be.w);

        padd.x += y.x; padd.y += y.y; padd.z += y.z; padd.w += y.w;
        pmax.x = fmaxf(pmax.x, y.x); pmax.y = fmaxf(pmax.y, y.y);
        pmax.z = fmaxf(pmax.z, y.z); pmax.w = fmaxf(pmax.w, y.w);
        pcnt++;
    }
    pool_flush(curg, f, padd, pmax, pcnt, lane);
}

// One block per graph: build [mean|add|max], MLP head, then re-zero this
// graph's pool slots (zero-on-entry invariant for the next replay).
__global__ void k_final(const float* __restrict__ W1, const float* __restrict__ b1,
                        const float* __restrict__ W2, const float* __restrict__ b2,
                        const float* __restrict__ W3, const float* __restrict__ b3,
                        float* __restrict__ out) {
    __shared__ float gv[3 * HH];
    __shared__ float l1[HH];
    __shared__ float l2[HH / 2];
    int g = blockIdx.x;
    int t = threadIdx.x;  // 128

    int cnt = g_counts[g];
    float ad = g_addpool[g * HH + t];
    float mean = ad / fmaxf((float)cnt, 1.f);
    float mx = (cnt > 0) ? fdec(g_maxpool[g * HH + t]) : 0.f;
    gv[t] = mean;
    gv[HH + t] = ad;
    gv[2 * HH + t] = mx;
    __syncthreads();

    // re-zero pools for next replay (all reads of this graph's slots are done)
    g_addpool[g * HH + t] = 0.f;
    g_maxpool[g * HH + t] = 0u;
    if (t == 0) g_counts[g] = 0;

    float acc = __ldg(&b1[t]);
    for (int k = 0; k < 3 * HH; k++)
        acc = fmaf(gv[k], __ldg(&W1[k * HH + t]), acc);
    l1[t] = fmaxf(acc, 0.f);
    __syncthreads();

    if (t < HH / 2) {
        float a2 = __ldg(&b2[t]);
        for (int k = 0; k < HH; k++)
            a2 = fmaf(l1[k], __ldg(&W2[k * (HH / 2) + t]), a2);
        l2[t] = fmaxf(a2, 0.f);
    }
    __syncthreads();

    if (t < OO) {
        float a3 = __ldg(&b3[t]);
        for (int k = 0; k < HH / 2; k++)
            a3 = fmaf(l2[k], __ldg(&W3[k * OO + t]), a3);
        out[g * OO + t] = a3;
    }
}

// ---------------- launch ----------------
extern "C" void kernel_launch(void* const* d_in, const int* in_sizes, int n_in,
                              void* d_out, int out_size) {
    const float* x     = (const float*)d_in[0];
    const int*   ei    = (const int*)d_in[1];
    const int*   batch = (const int*)d_in[2];
    int idx = 3;
    if (n_in > 3 && in_sizes[3] == 1) idx = 4;
    const float* Wg    = (const float*)d_in[idx++];
    const float* bg    = (const float*)d_in[idx++];
    const float* gamma = (const float*)d_in[idx++];
    const float* beta  = (const float*)d_in[idx++];
    const float* W1    = (const float*)d_in[idx++];
    const float* b1    = (const float*)d_in[idx++];
    const float* W2    = (const float*)d_in[idx++];
    const float* b2    = (const float*)d_in[idx++];
    const float* W3    = (const float*)d_in[idx++];
    const float* b3    = (const float*)d_in[idx++];
    float* out = (float*)d_out;

    static cudaStream_t s2 = nullptr;
    static cudaEvent_t ev1 = nullptr, ev2 = nullptr;
    if (!s2) {
        cudaStreamCreateWithFlags(&s2, cudaStreamNonBlocking);
        cudaEventCreateWithFlags(&ev1, cudaEventDisableTiming);
        cudaEventCreateWithFlags(&ev2, cudaEventDisableTiming);
    }

    const int smem = (DD * HH + 16 * 72) * (int)sizeof(float);
    cudaFuncSetAttribute(k_gemm, cudaFuncAttributeMaxDynamicSharedMemorySize, smem);

    // fork: gemm (reads only x, W) runs concurrent with the CSR build chain
    cudaEventRecord(ev1, 0);
    cudaStreamWaitEvent(s2, ev1, 0);
    k_gemm<<<NN / 64, 256, smem, s2>>>(x, Wg);
    cudaEventRecord(ev2, s2);

    k_deg<<<(EE / 4 + 255) / 256, 256>>>(ei);
    k_scanA<<<SBLK, 256>>>();
    k_scanC<<<SBLK, 256>>>();
    k_place<<<(EE / 4 + 255) / 256, 256>>>(ei);

    cudaStreamWaitEvent(0, ev2, 0);   // join
    k_agg<<<NN / (NPW * 8), 256>>>(batch, bg, gamma, beta);
    k_final<<<GG, 128>>>(W1, b1, W2, b2, W3, b3, out);
}

// round 13
// speedup vs baseline: 1.0849x; 1.0849x over previous
#include <cuda_runtime.h>
#include <cuda_fp16.h>
#include <cstdint>
#include <cfloat>

#define NN 40000
#define EE 640000
#define GG 64
#define DD 128
#define HH 128
#define OO 10
#define NPW 4            // nodes per warp in k_agg
#define SBLK 157         // scan blocks: ceil(40000/256)

typedef unsigned long long ull;

// ---------------- scratch (static device globals; no allocations) ----------------
__device__ __half   g_h[NN * HH];      // x @ W_gcn, fp16 (10.2 MB; halves L2 gather bytes)
__device__ int      g_degi[NN];
__device__ float    g_dinv[NN];
__device__ int      g_off[NN + 1];     // CSR row offsets (by dst)
__device__ int      g_cursor[NN];
__device__ int2     g_edge[EE];        // CSR: (src, bits(dinv[src]))
__device__ int      g_bsum[SBLK];      // scan partials
__device__ int      g_bbase[SBLK];
__device__ float    g_addpool[GG * HH];
__device__ unsigned g_maxpool[GG * HH];
__device__ int      g_counts[GG];

// order-preserving float <-> unsigned encoding for atomicMax
__device__ __forceinline__ unsigned fkey(float f) {
    int i = __float_as_int(f);
    return (unsigned)(i ^ ((i >> 31) | 0x80000000));
}
__device__ __forceinline__ float fdec(unsigned k) {
    int i = (k & 0x80000000u) ? (int)(k ^ 0x80000000u) : (int)(~k);
    return __int_as_float(i);
}

// packed f32x2 helpers (PTX-only; ptxas never emits FFMA2 from C++)
__device__ __forceinline__ ull pk2(float lo, float hi) {
    ull r; asm("mov.b64 %0, {%1, %2};" : "=l"(r) : "f"(lo), "f"(hi)); return r;
}
__device__ __forceinline__ void upk2(ull v, float& lo, float& hi) {
    asm("mov.b64 {%0, %1}, %2;" : "=f"(lo), "=f"(hi) : "l"(v));
}
__device__ __forceinline__ ull ffma2(ull a, ull b, ull c) {
    ull d; asm("fma.rn.f32x2 %0, %1, %2, %3;" : "=l"(d) : "l"(a), "l"(b), "l"(c));
    return d;
}

// load 4 consecutive halves as float4 (one 64-bit LDG + 2 cvt)
__device__ __forceinline__ float4 ldh4(const __half* p) {
    uint2 u = *(const uint2*)p;
    float2 a = __half22float2(*(const __half2*)&u.x);
    float2 b = __half22float2(*(const __half2*)&u.y);
    return make_float4(a.x, a.y, b.x, b.y);
}

// ---------------- kernels ----------------
__global__ void k_init() {
    int i = blockIdx.x * blockDim.x + threadIdx.x;
    if (i < NN)      g_degi[i] = 0;
    if (i < GG * HH) { g_addpool[i] = 0.f; g_maxpool[i] = 0u; }
    if (i < GG)      g_counts[i] = 0;
}

// 4 edges per thread via int4 loads (EE % 4 == 0): 4 atomics in flight.
__global__ void k_deg(const int* __restrict__ ei) {
    int t = blockIdx.x * blockDim.x + threadIdx.x;
    if (t >= EE / 4) return;
    int4 d = ((const int4*)(ei + EE))[t];
    atomicAdd(&g_degi[d.x], 1);
    atomicAdd(&g_degi[d.y], 1);
    atomicAdd(&g_degi[d.z], 1);
    atomicAdd(&g_degi[d.w], 1);
}

// ---- 3-phase multi-block exclusive scan of g_degi -> g_off ----
__global__ void k_scanA() {
    __shared__ int s[256];
    int t = threadIdx.x;
    int idx = blockIdx.x * 256 + t;
    int d = (idx < NN) ? g_degi[idx] : 0;
    s[t] = d;
    __syncthreads();
#pragma unroll
    for (int o = 1; o < 256; o <<= 1) {
        int v = (t >= o) ? s[t - o] : 0;
        __syncthreads();
        s[t] += v;
        __syncthreads();
    }
    if (idx < NN) g_off[idx] = s[t] - d;      // block-local exclusive prefix
    if (t == 255) g_bsum[blockIdx.x] = s[255];
}

__global__ void k_scanB() {
    __shared__ int s[256];
    int t = threadIdx.x;
    int d = (t < SBLK) ? g_bsum[t] : 0;
    s[t] = d;
    __syncthreads();
#pragma unroll
    for (int o = 1; o < 256; o <<= 1) {
        int v = (t >= o) ? s[t - o] : 0;
        __syncthreads();
        s[t] += v;
        __syncthreads();
    }
    if (t < SBLK) g_bbase[t] = s[t] - d;      // exclusive base per block
    if (t == SBLK - 1) g_off[NN] = s[t];
}

__global__ void k_scanC() {
    int idx = blockIdx.x * 256 + threadIdx.x;
    if (idx >= NN) return;
    int o = g_off[idx] + g_bbase[blockIdx.x];
    g_off[idx] = o;
    g_cursor[idx] = o;
    g_dinv[idx] = rsqrtf((float)g_degi[idx] + 1.0f);
}

// 4 edges per thread: 4 independent cursor atomics + 4 stores in flight.
__global__ void k_place(const int* __restrict__ ei) {
    int t = blockIdx.x * blockDim.x + threadIdx.x;
    if (t >= EE / 4) return;
    int4 s4 = ((const int4*)ei)[t];             // 4 src
    int4 d4 = ((const int4*)(ei + EE))[t];      // 4 dst
    int p0 = atomicAdd(&g_cursor[d4.x], 1);
    int p1 = atomicAdd(&g_cursor[d4.y], 1);
    int p2 = atomicAdd(&g_cursor[d4.z], 1);
    int p3 = atomicAdd(&g_cursor[d4.w], 1);
    float c0 = g_dinv[s4.x], c1 = g_dinv[s4.y];
    float c2 = g_dinv[s4.z], c3 = g_dinv[s4.w];
    g_edge[p0] = make_int2(s4.x, __float_as_int(c0));
    g_edge[p1] = make_int2(s4.y, __float_as_int(c1));
    g_edge[p2] = make_int2(s4.z, __float_as_int(c2));
    g_edge[p3] = make_int2(s4.w, __float_as_int(c3));
}

// h = x @ W. 64x128 tile, 256 threads, packed f32x2 FFMA; fp16 output store.
__global__ void k_gemm(const float* __restrict__ x, const float* __restrict__ W) {
    extern __shared__ float sm[];
    float* Ws = sm;                 // 128*128
    float* Xs = sm + DD * HH;       // 16 * 72 (transposed x tile)
    const int XLD = 72;
    int tid = threadIdx.x;
    int row0 = blockIdx.x * 64;

    for (int i = tid; i < (DD * HH) / 4; i += 256)
        ((float4*)Ws)[i] = ((const float4*)W)[i];

    int tx = tid & 31;              // cols tx*4 .. tx*4+3
    int ty = tid >> 5;              // rows ty*8 .. ty*8+7 (as 4 pairs)
    ull acc[4][4];                  // [row-pair][col]
#pragma unroll
    for (int rp = 0; rp < 4; rp++)
#pragma unroll
        for (int c = 0; c < 4; c++) acc[rp][c] = 0ULL;

    int lr = tid >> 2, lk = tid & 3;
    for (int kt = 0; kt < DD; kt += 16) {
        __syncthreads();
        float4 xv = *(const float4*)(x + (size_t)(row0 + lr) * DD + kt + lk * 4);
        Xs[(lk * 4 + 0) * XLD + lr] = xv.x;
        Xs[(lk * 4 + 1) * XLD + lr] = xv.y;
        Xs[(lk * 4 + 2) * XLD + lr] = xv.z;
        Xs[(lk * 4 + 3) * XLD + lr] = xv.w;
        __syncthreads();
#pragma unroll
        for (int kk = 0; kk < 16; kk++) {
            float4 wv = *(const float4*)(Ws + (kt + kk) * HH + tx * 4);
            ulonglong2 xa = *(const ulonglong2*)(Xs + kk * XLD + ty * 8);
            ulonglong2 xb = *(const ulonglong2*)(Xs + kk * XLD + ty * 8 + 4);
            ull xp[4] = {xa.x, xa.y, xb.x, xb.y};
            ull w0 = pk2(wv.x, wv.x), w1 = pk2(wv.y, wv.y);
            ull w2 = pk2(wv.z, wv.z), w3 = pk2(wv.w, wv.w);
#pragma unroll
            for (int rp = 0; rp < 4; rp++) {
                acc[rp][0] = ffma2(xp[rp], w0, acc[rp][0]);
                acc[rp][1] = ffma2(xp[rp], w1, acc[rp][1]);
                acc[rp][2] = ffma2(xp[rp], w2, acc[rp][2]);
                acc[rp][3] = ffma2(xp[rp], w3, acc[rp][3]);
            }
        }
    }
#pragma unroll
    for (int rp = 0; rp < 4; rp++) {
        float l0, h0, l1, h1, l2, h2, l3, h3;
        upk2(acc[rp][0], l0, h0);
        upk2(acc[rp][1], l1, h1);
        upk2(acc[rp][2], l2, h2);
        upk2(acc[rp][3], l3, h3);
        size_t r = (size_t)(row0 + ty * 8 + 2 * rp) * HH + tx * 4;
        __half2 a01 = __floats2half2_rn(l0, l1);
        __half2 a23 = __floats2half2_rn(l2, l3);
        __half2 b01 = __floats2half2_rn(h0, h1);
        __half2 b23 = __floats2half2_rn(h2, h3);
        *(uint2*)(g_h + r)      = make_uint2(*(unsigned*)&a01, *(unsigned*)&a23);
        *(uint2*)(g_h + r + HH) = make_uint2(*(unsigned*)&b01, *(unsigned*)&b23);
    }
}

__device__ __forceinline__ void pool_flush(int g, int f, float4 padd, float4 pmax,
                                           int pcnt, int lane) {
    float* p = g_addpool + g * HH + f;
    asm volatile("red.global.add.v4.f32 [%0], {%1, %2, %3, %4};"
                 :: "l"(p), "f"(padd.x), "f"(padd.y), "f"(padd.z), "f"(padd.w)
                 : "memory");
    unsigned* mp = g_maxpool + g * HH + f;
    atomicMax(mp + 0, fkey(pmax.x));
    atomicMax(mp + 1, fkey(pmax.y));
    atomicMax(mp + 2, fkey(pmax.z));
    atomicMax(mp + 3, fkey(pmax.w));
    if (lane == 0) atomicAdd(&g_counts[g], pcnt);
}

// One warp per NPW consecutive nodes: 2-wide CSR gather-reduce (fp16 rows,
// fp32 math) + self loop + bias + ReLU + LayerNorm + register pooling.
// Structure identical to the R6 measured-best kernel.
__global__ void __launch_bounds__(256) k_agg(const int* __restrict__ batch,
                                             const float* __restrict__ bgcn,
                                             const float* __restrict__ gamma,
                                             const float* __restrict__ beta) {
    int warp = blockIdx.x * 8 + (threadIdx.x >> 5);
    int n0 = warp * NPW;
    if (n0 >= NN) return;
    int lane = threadIdx.x & 31;
    int f = lane * 4;

    float4 bb = *(const float4*)(bgcn + f);
    float4 ga = *(const float4*)(gamma + f);
    float4 be = *(const float4*)(beta + f);

    float4 padd = make_float4(0.f, 0.f, 0.f, 0.f);
    float4 pmax = make_float4(-FLT_MAX, -FLT_MAX, -FLT_MAX, -FLT_MAX);
    int pcnt = 0;
    int curg = __ldg(&batch[n0]);

#pragma unroll
    for (int k = 0; k < NPW; k++) {
        int n = n0 + k;
        int g = __ldg(&batch[n]);
        if (g != curg) {
            pool_flush(curg, f, padd, pmax, pcnt, lane);
            padd = make_float4(0.f, 0.f, 0.f, 0.f);
            pmax = make_float4(-FLT_MAX, -FLT_MAX, -FLT_MAX, -FLT_MAX);
            pcnt = 0;
            curg = g;
        }
        int s = __ldg(&g_off[n]);
        int e = __ldg(&g_off[n + 1]);
        float4 a0 = make_float4(0.f, 0.f, 0.f, 0.f);
        float4 a1 = make_float4(0.f, 0.f, 0.f, 0.f);
        int j = s;
        if ((j & 1) && j < e) {             // align to int4 boundary
            int2 p = __ldg(&g_edge[j]);
            float c = __int_as_float(p.y);
            float4 v = ldh4(g_h + (size_t)p.x * HH + f);
            a0.x = fmaf(c, v.x, a0.x); a0.y = fmaf(c, v.y, a0.y);
            a0.z = fmaf(c, v.z, a0.z); a0.w = fmaf(c, v.w, a0.w);
            j++;
        }
        for (; j + 2 <= e; j += 2) {        // 2 independent gathers in flight
            int4 q = *(const int4*)(g_edge + j);   // two edges, one broadcast ld
            float4 v0 = ldh4(g_h + (size_t)q.x * HH + f);
            float4 v1 = ldh4(g_h + (size_t)q.z * HH + f);
            float c0 = __int_as_float(q.y), c1 = __int_as_float(q.w);
            a0.x = fmaf(c0, v0.x, a0.x); a0.y = fmaf(c0, v0.y, a0.y);
            a0.z = fmaf(c0, v0.z, a0.z); a0.w = fmaf(c0, v0.w, a0.w);
            a1.x = fmaf(c1, v1.x, a1.x); a1.y = fmaf(c1, v1.y, a1.y);
            a1.z = fmaf(c1, v1.z, a1.z); a1.w = fmaf(c1, v1.w, a1.w);
        }
        if (j < e) {                        // tail (at most 1)
            int2 p = __ldg(&g_edge[j]);
            float c = __int_as_float(p.y);
            float4 v = ldh4(g_h + (size_t)p.x * HH + f);
            a0.x = fmaf(c, v.x, a0.x); a0.y = fmaf(c, v.y, a0.y);
            a0.z = fmaf(c, v.z, a0.z); a0.w = fmaf(c, v.w, a0.w);
        }
        float4 acc = make_float4(a0.x + a1.x, a0.y + a1.y,
                                 a0.z + a1.z, a0.w + a1.w);

        float di = g_dinv[n];
        float4 hv = ldh4(g_h + (size_t)n * HH + f);
        float4 v;
        v.x = fmaxf(fmaf(fmaf(hv.x, di, acc.x), di, bb.x), 0.f);
        v.y = fmaxf(fmaf(fmaf(hv.y, di, acc.y), di, bb.y), 0.f);
        v.z = fmaxf(fmaf(fmaf(hv.z, di, acc.z), di, bb.z), 0.f);
        v.w = fmaxf(fmaf(fmaf(hv.w, di, acc.w), di, bb.w), 0.f);

        float ssum = v.x + v.y + v.z + v.w;
        float qsum = v.x * v.x + v.y * v.y + v.z * v.z + v.w * v.w;
#pragma unroll
        for (int o = 16; o; o >>= 1) {
            ssum += __shfl_xor_sync(0xffffffffu, ssum, o);
            qsum += __shfl_xor_sync(0xffffffffu, qsum, o);
        }
        float mean = ssum * (1.f / 128.f);
        float var  = qsum * (1.f / 128.f) - mean * mean;
        float rstd = rsqrtf(var + 1e-5f);

        float4 y;
        y.x = fmaf((v.x - mean) * rstd, ga.x, be.x);
        y.y = fmaf((v.y - mean) * rstd, ga.y, be.y);
        y.z = fmaf((v.z - mean) * rstd, ga.z, be.z);
        y.w = fmaf((v.w - mean) * rstd, ga.w, be.w);

        padd.x += y.x; padd.y += y.y; padd.z += y.z; padd.w += y.w;
        pmax.x = fmaxf(pmax.x, y.x); pmax.y = fmaxf(pmax.y, y.y);
        pmax.z = fmaxf(pmax.z, y.z); pmax.w = fmaxf(pmax.w, y.w);
        pcnt++;
    }
    pool_flush(curg, f, padd, pmax, pcnt, lane);
}

// One block per graph: build [mean|add|max] then 384->128->64->10 MLP.
__global__ void k_final(const float* __restrict__ W1, const float* __restrict__ b1,
                        const float* __restrict__ W2, const float* __restrict__ b2,
                        const float* __restrict__ W3, const float* __restrict__ b3,
                        float* __restrict__ out) {
    __shared__ float gv[3 * HH];
    __shared__ float l1[HH];
    __shared__ float l2[HH / 2];
    int g = blockIdx.x;
    int t = threadIdx.x;  // 128

    int cnt = g_counts[g];
    float ad = g_addpool[g * HH + t];
    float mean = ad / fmaxf((float)cnt, 1.f);
    float mx = (cnt > 0) ? fdec(g_maxpool[g * HH + t]) : 0.f;
    gv[t] = mean;
    gv[HH + t] = ad;
    gv[2 * HH + t] = mx;
    __syncthreads();

    float acc = __ldg(&b1[t]);
    for (int k = 0; k < 3 * HH; k++)
        acc = fmaf(gv[k], __ldg(&W1[k * HH + t]), acc);
    l1[t] = fmaxf(acc, 0.f);
    __syncthreads();

    if (t < HH / 2) {
        float a2 = __ldg(&b2[t]);
        for (int k = 0; k < HH; k++)
            a2 = fmaf(l1[k], __ldg(&W2[k * (HH / 2) + t]), a2);
        l2[t] = fmaxf(a2, 0.f);
    }
    __syncthreads();

    if (t < OO) {
        float a3 = __ldg(&b3[t]);
        for (int k = 0; k < HH / 2; k++)
            a3 = fmaf(l2[k], __ldg(&W3[k * OO + t]), a3);
        out[g * OO + t] = a3;
    }
}

// ---------------- launch ----------------
extern "C" void kernel_launch(void* const* d_in, const int* in_sizes, int n_in,
                              void* d_out, int out_size) {
    const float* x     = (const float*)d_in[0];
    const int*   ei    = (const int*)d_in[1];
    const int*   batch = (const int*)d_in[2];
    int idx = 3;
    if (n_in > 3 && in_sizes[3] == 1) idx = 4;
    const float* Wg    = (const float*)d_in[idx++];
    const float* bg    = (const float*)d_in[idx++];
    const float* gamma = (const float*)d_in[idx++];
    const float* beta  = (const float*)d_in[idx++];
    const float* W1    = (const float*)d_in[idx++];
    const float* b1    = (const float*)d_in[idx++];
    const float* W2    = (const float*)d_in[idx++];
    const float* b2    = (const float*)d_in[idx++];
    const float* W3    = (const float*)d_in[idx++];
    const float* b3    = (const float*)d_in[idx++];
    float* out = (float*)d_out;

    static cudaStream_t s2 = nullptr;
    static cudaEvent_t ev1 = nullptr, ev2 = nullptr;
    if (!s2) {
        cudaStreamCreateWithFlags(&s2, cudaStreamNonBlocking);
        cudaEventCreateWithFlags(&ev1, cudaEventDisableTiming);
        cudaEventCreateWithFlags(&ev2, cudaEventDisableTiming);
    }

    const int smem = (DD * HH + 16 * 72) * (int)sizeof(float);
    cudaFuncSetAttribute(k_gemm, cudaFuncAttributeMaxDynamicSharedMemorySize, smem);

    // fork: gemm (reads only x, W) runs concurrent with the CSR build chain
    cudaEventRecord(ev1, 0);
    cudaStreamWaitEvent(s2, ev1, 0);
    k_gemm<<<NN / 64, 256, smem, s2>>>(x, Wg);
    cudaEventRecord(ev2, s2);

    k_init<<<(NN + 255) / 256, 256>>>();
    k_deg<<<(EE / 4 + 255) / 256, 256>>>(ei);
    k_scanA<<<SBLK, 256>>>();
    k_scanB<<<1, 256>>>();
    k_scanC<<<SBLK, 256>>>();
    k_place<<<(EE / 4 + 255) / 256, 256>>>(ei);

    cudaStreamWaitEvent(0, ev2, 0);   // join
    k_agg<<<NN / (NPW * 8), 256>>>(batch, bg, gamma, beta);
    k_final<<<GG, 128>>>(W1, b1, W2, b2, W3, b3, out);
}